// round 3
// baseline (speedup 1.0000x reference)
#include <cuda_runtime.h>
#include <cstdint>

#define BATCH 64
#define SEQ   512
#define HID   300
#define UN    512
#define G3    1536
#define NBLK  128
#define UPB   4   // hidden units per block (NBLK*UPB == UN)

// ---- scratch (device globals: allocation is forbidden) ----
// g_xg is reused by both layers (layer0's projections are dead before layer1's
// projection GEMM runs) -> 201 MB instead of 402 MB.
__device__ float g_xg [SEQ * G3 * BATCH];   // input projections [s][col][b]
__device__ float g_y0 [SEQ * BATCH * UN];   // layer0 outputs [s][b][u]
__device__ float g_h  [2][BATCH * UN];      // ping-pong hidden state
__device__ unsigned g_barcnt;

__device__ __forceinline__ float sigm(float x) { return 1.f / (1.f + __expf(-x)); }

// ---------------------------------------------------------------------------
// init: zero hidden state + barrier counter (must run before each scan)
// ---------------------------------------------------------------------------
__global__ void init_k()
{
    int tid = blockIdx.x * blockDim.x + threadIdx.x;
    if (tid == 0) g_barcnt = 0u;
    for (int i = tid; i < BATCH * UN; i += gridDim.x * blockDim.x) {
        g_h[0][i] = 0.f;
        g_h[1][i] = 0.f;
    }
}

// ---------------------------------------------------------------------------
// Input projection GEMM: g_xg[s][col][b] = bias[col] + sum_k A[s,b][k]*W[k][col]
// mode 0: A row (s,b) = emb[tokens[b][s]]   (K = HID)
// mode 1: A row (s,b) = g_y0[s][b][:]       (K = UN)
// Tiles: 64(M=batch) x 64(N), BK=16, 256 threads, 4x4 per thread.
// ---------------------------------------------------------------------------
__global__ void __launch_bounds__(256) gemm_proj(
    const float* __restrict__ Asrc,     // emb (mode0) or unused (mode1)
    const int*   __restrict__ tokens,   // mode0 only
    const float* __restrict__ Wm,       // [K][G3]
    const float* __restrict__ bias,     // [G3] (input bias row b[0])
    int K, int mode)
{
    __shared__ float As[16][65];
    __shared__ float Bs[16][65];

    const int s   = blockIdx.y;
    const int n0  = blockIdx.x * 64;
    const int tid = threadIdx.x;
    const int tx  = tid & 15;
    const int ty  = tid >> 4;

    int am[4], ak[4];
    const float* arow[4];
    #pragma unroll
    for (int i = 0; i < 4; i++) {
        int id = tid + 256 * i;        // 0..1023
        am[i] = id >> 4;               // m (batch)
        ak[i] = id & 15;               // k within tile
        if (mode == 0) {
            int tok = tokens[am[i] * SEQ + s];
            arow[i] = Asrc + (size_t)tok * HID;
        } else {
            arow[i] = g_y0 + ((size_t)s * BATCH + am[i]) * UN;
        }
    }

    float acc[4][4];
    #pragma unroll
    for (int i = 0; i < 4; i++)
        #pragma unroll
        for (int j = 0; j < 4; j++) acc[i][j] = 0.f;

    for (int k0 = 0; k0 < K; k0 += 16) {
        #pragma unroll
        for (int i = 0; i < 4; i++) {
            int k = k0 + ak[i];
            As[ak[i]][am[i]] = (k < K) ? arow[i][k] : 0.f;
        }
        #pragma unroll
        for (int i = 0; i < 4; i++) {
            int id = tid + 256 * i;
            int kk = id >> 6;
            int nn = id & 63;
            int k  = k0 + kk;
            Bs[kk][nn] = (k < K) ? Wm[(size_t)k * G3 + n0 + nn] : 0.f;
        }
        __syncthreads();
        #pragma unroll
        for (int k = 0; k < 16; k++) {
            float a[4], bv[4];
            #pragma unroll
            for (int i = 0; i < 4; i++) a[i]  = As[k][ty * 4 + i];
            #pragma unroll
            for (int j = 0; j < 4; j++) bv[j] = Bs[k][tx * 4 + j];
            #pragma unroll
            for (int i = 0; i < 4; i++)
                #pragma unroll
                for (int j = 0; j < 4; j++)
                    acc[i][j] = fmaf(a[i], bv[j], acc[i][j]);
        }
        __syncthreads();
    }

    #pragma unroll
    for (int j = 0; j < 4; j++) {
        int col  = n0 + tx * 4 + j;
        float bb = bias[col];
        #pragma unroll
        for (int i = 0; i < 4; i++) {
            int m = ty * 4 + i;
            g_xg[((size_t)s * G3 + col) * BATCH + m] = acc[i][j] + bb;
        }
    }
}

// ---------------------------------------------------------------------------
// Persistent GRU scan. 128 blocks x 256 threads, all co-resident (<=148 SMs).
// Block bid owns hidden units u0..u0+3 (12 columns of U cached in SMEM, loaded
// once). Thread (b, ul): 3 gate dot-products (K=512) for one (batch, unit).
// h ping-pong in global; one grid barrier per step; h_prev kept in register.
// which==0: y -> g_y0 [s][b][u]
// which==1: y -> extout [b][s][u], h_last -> extout + B*S*U
// ---------------------------------------------------------------------------
__global__ void __launch_bounds__(256, 1) gru_scan(
    const float* __restrict__ Um,      // [UN][G3]
    const float* __restrict__ brec,    // [G3] (recurrent bias row b[1])
    int which,
    float* __restrict__ extout)
{
    __shared__ float Us[12][UN];       // 24 KB (z:0-3, r:4-7, h:8-11)
    __shared__ float hs[BATCH][65];    // 16.6 KB h tile (pad 65)

    const int tid = threadIdx.x;
    const int b   = tid & 63;
    const int ul  = tid >> 6;
    const int u0  = blockIdx.x * UPB;
    const int u   = u0 + ul;

    for (int idx = tid; idx < 12 * UN; idx += 256) {
        int j = idx >> 9;              // / UN
        int k = idx & (UN - 1);
        int col = (j >> 2) * UN + u0 + (j & 3);
        Us[j][k] = Um[(size_t)k * G3 + col];
    }
    const float bz = brec[u];
    const float br = brec[UN + u];
    const float bh = brec[2 * UN + u];
    __syncthreads();

    const unsigned nblk = gridDim.x;
    float hprev = 0.f;                 // this thread owns (b,u): h[t-1][b][u]

    for (int t = 0; t < SEQ; t++) {
        const float* hr = g_h[t & 1];
        float*       hw = g_h[(t + 1) & 1];

        // hoist gate-input loads (DRAM-latency overlap with FMA body)
        const float* xgt = g_xg + (size_t)t * G3 * BATCH;
        const float xz = xgt[(0 * UN + u) * BATCH + b];
        const float xr = xgt[(1 * UN + u) * BATCH + b];
        const float xh = xgt[(2 * UN + u) * BATCH + b];

        float az = 0.f, ar = 0.f, ah = 0.f;

        #pragma unroll 1
        for (int kt = 0; kt < UN; kt += 64) {
            // cooperative tile load (L2-only: other SMs wrote h last step)
            #pragma unroll
            for (int i = 0; i < 4; i++) {
                int id  = tid + 256 * i;
                int row = id >> 4;
                int f4  = (id & 15) * 4;
                float4 v = __ldcv(reinterpret_cast<const float4*>(hr + row * UN + kt + f4));
                hs[row][f4 + 0] = v.x; hs[row][f4 + 1] = v.y;
                hs[row][f4 + 2] = v.z; hs[row][f4 + 3] = v.w;
            }
            __syncthreads();
            #pragma unroll
            for (int k = 0; k < 64; k += 4) {
                const float4 uz = *reinterpret_cast<const float4*>(&Us[ul    ][kt + k]);
                const float4 ur = *reinterpret_cast<const float4*>(&Us[4 + ul][kt + k]);
                const float4 uh = *reinterpret_cast<const float4*>(&Us[8 + ul][kt + k]);
                const float h0 = hs[b][k], h1 = hs[b][k + 1];
                const float h2 = hs[b][k + 2], h3 = hs[b][k + 3];
                az = fmaf(h0, uz.x, az); az = fmaf(h1, uz.y, az);
                az = fmaf(h2, uz.z, az); az = fmaf(h3, uz.w, az);
                ar = fmaf(h0, ur.x, ar); ar = fmaf(h1, ur.y, ar);
                ar = fmaf(h2, ur.z, ar); ar = fmaf(h3, ur.w, ar);
                ah = fmaf(h0, uh.x, ah); ah = fmaf(h1, uh.y, ah);
                ah = fmaf(h2, uh.z, ah); ah = fmaf(h3, uh.w, ah);
            }
            __syncthreads();
        }

        // gates (Keras reset_after): rg = h@U + b[1]
        const float z  = sigm(xz + az + bz);
        const float r  = sigm(xr + ar + br);
        const float hh = tanhf(xh + r * (ah + bh));
        const float hnew = z * hprev + (1.f - z) * hh;
        hprev = hnew;

        hw[b * UN + u] = hnew;
        if (which == 0) {
            g_y0[((size_t)t * BATCH + b) * UN + u] = hnew;
        } else {
            extout[((size_t)b * SEQ + t) * UN + u] = hnew;
            if (t == SEQ - 1)
                extout[(size_t)BATCH * SEQ * UN + b * UN + u] = hnew;
        }

        // grid barrier (monotonic counter; reset by init_k each launch)
        __threadfence();
        __syncthreads();
        if (tid == 0) {
            atomicAdd(&g_barcnt, 1u);
            const unsigned target = nblk * (unsigned)(t + 1);
            while (*((volatile unsigned*)&g_barcnt) < target) { __nanosleep(32); }
        }
        __syncthreads();
        __threadfence();
    }
}

// ---------------------------------------------------------------------------
extern "C" void kernel_launch(void* const* d_in, const int* in_sizes, int n_in,
                              void* d_out, int out_size)
{
    const int*   tokens = (const int*)  d_in[0];
    const float* emb    = (const float*)d_in[1];
    const float* W0     = (const float*)d_in[2];
    const float* U0     = (const float*)d_in[3];
    const float* b0     = (const float*)d_in[4];
    const float* W1     = (const float*)d_in[5];
    const float* U1     = (const float*)d_in[6];
    const float* b1     = (const float*)d_in[7];
    float* out = (float*)d_out;

    dim3 gg(G3 / 64, SEQ);

    // layer 0: xg = gather(emb, tokens) @ W0 + b0[0]
    gemm_proj<<<gg, 256>>>(emb, tokens, W0, b0, HID, 0);
    init_k<<<32, 256>>>();
    gru_scan<<<NBLK, 256>>>(U0, b0 + G3, 0, nullptr);

    // layer 1: xg = y0 @ W1 + b1[0]   (g_xg reused)
    gemm_proj<<<gg, 256>>>(nullptr, nullptr, W1, b1, UN, 1);
    init_k<<<32, 256>>>();
    gru_scan<<<NBLK, 256>>>(U1, b1 + G3, 1, out);
}

// round 6
// speedup vs baseline: 1.0565x; 1.0565x over previous
#include <cuda_runtime.h>
#include <cstdint>

#define BATCH 64
#define SEQ   512
#define HID   300
#define UN    512
#define G3    1536
#define NBLK  128
#define UPB   4   // hidden units per block (NBLK*UPB == UN)

// ---- scratch (device globals: allocation is forbidden) ----
__device__ float g_xg [SEQ * G3 * BATCH];   // input projections [s][col][b] (reused by both layers)
__device__ float g_y0 [SEQ * BATCH * UN];   // layer0 outputs [s][b][u]
__device__ float g_h  [2][BATCH * UN];      // ping-pong hidden state
__device__ unsigned g_barcnt;

__device__ __forceinline__ float sigm(float x) { return 1.f / (1.f + __expf(-x)); }

// ---------------------------------------------------------------------------
// init: zero hidden state + barrier counter (must run before each scan)
// ---------------------------------------------------------------------------
__global__ void init_k()
{
    int tid = blockIdx.x * blockDim.x + threadIdx.x;
    if (tid == 0) g_barcnt = 0u;
    for (int i = tid; i < BATCH * UN; i += gridDim.x * blockDim.x) {
        g_h[0][i] = 0.f;
        g_h[1][i] = 0.f;
    }
}

// ---------------------------------------------------------------------------
// Input projection GEMM: g_xg[s][col][b] = bias[col] + sum_k A[s,b][k]*W[k][col]
// mode 0: A row (s,b) = emb[tokens[b][s]]   (K = HID)
// mode 1: A row (s,b) = g_y0[s][b][:]       (K = UN)
// Tile: 64(M=batch) x 128(N), BK=8, double-buffered, 256 threads, 8x4/thread.
// Epilogue transposes through SMEM so [col][b] stores are coalesced float4.
// ---------------------------------------------------------------------------
__global__ void __launch_bounds__(256) gemm_proj(
    const float* __restrict__ Asrc,     // emb (mode0) or unused (mode1)
    const int*   __restrict__ tokens,   // mode0 only
    const float* __restrict__ Wm,       // [K][G3]
    const float* __restrict__ bias,     // [G3] (input bias row b[0])
    int K, int mode)
{
    __shared__ float As[2][8][64];      // [buf][k][m]   4 KB
    __shared__ float Bs[2][8][128];     // [buf][k][n]   8 KB
    __shared__ float trans[128][68];    // [col][m] epilogue transpose  34 KB

    const int s   = blockIdx.y;
    const int n0g = blockIdx.x * 128;
    const int tid = threadIdx.x;

    // per-thread compute tile: 8 m x 4 n
    const int m0 = (tid >> 5) * 8;      // warp-uniform (broadcast A loads)
    const int n0 = (tid & 31) * 4;

    // A staging: this thread loads (m_a, k_a0) and (m_a, k_a0+4) each tile
    const int m_a  = tid & 63;
    const int k_a0 = tid >> 6;          // 0..3
    const int k_a1 = k_a0 + 4;          // 4..7
    const float* arow;
    if (mode == 0) {
        int tok = tokens[m_a * SEQ + s];
        arow = Asrc + (size_t)tok * HID;
    } else {
        arow = g_y0 + ((size_t)s * BATCH + m_a) * UN;
    }
    // B staging: this thread loads one float4 at (k_b, n_b)
    const int k_b = tid >> 5;           // 0..7
    const int n_b = (tid & 31) * 4;

    float acc[8][4];
    #pragma unroll
    for (int i = 0; i < 8; i++)
        #pragma unroll
        for (int j = 0; j < 4; j++) acc[i][j] = 0.f;

    const int Ksteps = (K + 7) / 8;

    // prologue: tile 0 -> buf 0
    As[0][k_a0][m_a] = (k_a0 < K) ? arow[k_a0] : 0.f;
    As[0][k_a1][m_a] = (k_a1 < K) ? arow[k_a1] : 0.f;
    {
        float4 b4 = {0.f, 0.f, 0.f, 0.f};
        if (k_b < K) b4 = *reinterpret_cast<const float4*>(Wm + (size_t)k_b * G3 + n0g + n_b);
        *reinterpret_cast<float4*>(&Bs[0][k_b][n_b]) = b4;
    }
    __syncthreads();

    int buf = 0;
    for (int kt = 0; kt < Ksteps; kt++) {
        // prefetch next tile into registers
        float pa0 = 0.f, pa1 = 0.f;
        float4 pb = {0.f, 0.f, 0.f, 0.f};
        const int nk = (kt + 1) * 8;
        if (kt + 1 < Ksteps) {
            int ka = nk + k_a0; if (ka < K) pa0 = arow[ka];
            ka = nk + k_a1;     if (ka < K) pa1 = arow[ka];
            int kb = nk + k_b;
            if (kb < K) pb = *reinterpret_cast<const float4*>(Wm + (size_t)kb * G3 + n0g + n_b);
        }

        // compute on current buffer
        #pragma unroll
        for (int k = 0; k < 8; k++) {
            const float4 b4 = *reinterpret_cast<const float4*>(&Bs[buf][k][n0]);
            const float4 a0 = *reinterpret_cast<const float4*>(&As[buf][k][m0]);
            const float4 a1 = *reinterpret_cast<const float4*>(&As[buf][k][m0 + 4]);
            const float av[8] = {a0.x, a0.y, a0.z, a0.w, a1.x, a1.y, a1.z, a1.w};
            const float bv[4] = {b4.x, b4.y, b4.z, b4.w};
            #pragma unroll
            for (int i = 0; i < 8; i++)
                #pragma unroll
                for (int j = 0; j < 4; j++)
                    acc[i][j] = fmaf(av[i], bv[j], acc[i][j]);
        }

        // store prefetched tile into other buffer
        if (kt + 1 < Ksteps) {
            As[buf ^ 1][k_a0][m_a] = pa0;
            As[buf ^ 1][k_a1][m_a] = pa1;
            *reinterpret_cast<float4*>(&Bs[buf ^ 1][k_b][n_b]) = pb;
        }
        __syncthreads();
        buf ^= 1;
    }

    // epilogue: transpose via SMEM, add bias, coalesced float4 stores
    #pragma unroll
    for (int i = 0; i < 8; i++)
        #pragma unroll
        for (int j = 0; j < 4; j++)
            trans[n0 + j][m0 + i] = acc[i][j];
    __syncthreads();

    #pragma unroll
    for (int it = 0; it < 8; it++) {
        int id  = tid + 256 * it;       // 0..2047 float4s
        int col = id >> 4;              // 0..127
        int m4  = (id & 15) * 4;        // 0..60
        float4 v = *reinterpret_cast<const float4*>(&trans[col][m4]);
        float bb = bias[n0g + col];
        v.x += bb; v.y += bb; v.z += bb; v.w += bb;
        *reinterpret_cast<float4*>(g_xg + ((size_t)s * G3 + n0g + col) * BATCH + m4) = v;
    }
}

// ---------------------------------------------------------------------------
// Persistent GRU scan. 128 blocks x 256 threads, all co-resident (<=148 SMs).
// Block bid owns hidden units u0..u0+3 (12 columns of U cached in SMEM, loaded
// once). Thread (b, ul): 3 gate dot-products (K=512) for one (batch, unit).
// h ping-pong in global; one grid barrier per step; h_prev kept in register;
// next step's xg loads prefetched before the barrier.
// which==0: y -> g_y0 [s][b][u]
// which==1: y -> extout [b][s][u], h_last -> extout + B*S*U
// ---------------------------------------------------------------------------
__global__ void __launch_bounds__(256, 1) gru_scan(
    const float* __restrict__ Um,      // [UN][G3]
    const float* __restrict__ brec,    // [G3] (recurrent bias row b[1])
    int which,
    float* __restrict__ extout)
{
    __shared__ float Us[12][UN];       // 24 KB (z:0-3, r:4-7, h:8-11)
    __shared__ float hs[BATCH][68];    // 17.4 KB h tile (stride 68: float4-aligned,
                                       // phase-conflict-free for hs[b][k] reads)

    const int tid = threadIdx.x;
    const int b   = tid & 63;
    const int ul  = tid >> 6;
    const int u0  = blockIdx.x * UPB;
    const int u   = u0 + ul;

    for (int idx = tid; idx < 12 * UN; idx += 256) {
        int j = idx >> 9;              // / UN
        int k = idx & (UN - 1);
        int col = (j >> 2) * UN + u0 + (j & 3);
        Us[j][k] = Um[(size_t)k * G3 + col];
    }
    const float bz = brec[u];
    const float br = brec[UN + u];
    const float bh = brec[2 * UN + u];
    __syncthreads();

    const unsigned nblk = gridDim.x;
    float hprev = 0.f;                 // this thread owns (b,u): h[t-1][b][u]

    // preload step-0 gate inputs
    float xz = g_xg[((size_t)0 * G3 + 0 * UN + u) * BATCH + b];
    float xr = g_xg[((size_t)0 * G3 + 1 * UN + u) * BATCH + b];
    float xh = g_xg[((size_t)0 * G3 + 2 * UN + u) * BATCH + b];

    for (int t = 0; t < SEQ; t++) {
        const float* hr = g_h[t & 1];
        float*       hw = g_h[(t + 1) & 1];

        float az = 0.f, ar = 0.f, ah = 0.f;

        #pragma unroll 1
        for (int kt = 0; kt < UN; kt += 64) {
            // cooperative tile load (L2-only: other SMs wrote h last step)
            #pragma unroll
            for (int i = 0; i < 4; i++) {
                int id  = tid + 256 * i;
                int row = id >> 4;
                int f4  = (id & 15) * 4;
                float4 v = __ldcv(reinterpret_cast<const float4*>(hr + row * UN + kt + f4));
                *reinterpret_cast<float4*>(&hs[row][f4]) = v;
            }
            __syncthreads();
            #pragma unroll
            for (int k = 0; k < 64; k += 4) {
                const float4 uz = *reinterpret_cast<const float4*>(&Us[ul    ][kt + k]);
                const float4 ur = *reinterpret_cast<const float4*>(&Us[4 + ul][kt + k]);
                const float4 uh = *reinterpret_cast<const float4*>(&Us[8 + ul][kt + k]);
                const float4 hv = *reinterpret_cast<const float4*>(&hs[b][k]);
                az = fmaf(hv.x, uz.x, az); az = fmaf(hv.y, uz.y, az);
                az = fmaf(hv.z, uz.z, az); az = fmaf(hv.w, uz.w, az);
                ar = fmaf(hv.x, ur.x, ar); ar = fmaf(hv.y, ur.y, ar);
                ar = fmaf(hv.z, ur.z, ar); ar = fmaf(hv.w, ur.w, ar);
                ah = fmaf(hv.x, uh.x, ah); ah = fmaf(hv.y, uh.y, ah);
                ah = fmaf(hv.z, uh.z, ah); ah = fmaf(hv.w, uh.w, ah);
            }
            __syncthreads();
        }

        // gates (Keras reset_after): rg = h@U + b[1]
        const float z  = sigm(xz + az + bz);
        const float r  = sigm(xr + ar + br);
        const float hh = tanhf(xh + r * (ah + bh));
        const float hnew = z * hprev + (1.f - z) * hh;
        hprev = hnew;

        // prefetch next step's gate inputs (independent of h / barrier)
        if (t + 1 < SEQ) {
            const float* xgn = g_xg + (size_t)(t + 1) * G3 * BATCH;
            xz = __ldg(xgn + ((size_t)0 * UN + u) * BATCH + b);
            xr = __ldg(xgn + ((size_t)1 * UN + u) * BATCH + b);
            xh = __ldg(xgn + ((size_t)2 * UN + u) * BATCH + b);
        }

        hw[b * UN + u] = hnew;
        if (which == 0) {
            g_y0[((size_t)t * BATCH + b) * UN + u] = hnew;
        } else {
            extout[((size_t)b * SEQ + t) * UN + u] = hnew;
            if (t == SEQ - 1)
                extout[(size_t)BATCH * SEQ * UN + b * UN + u] = hnew;
        }

        // grid barrier (monotonic counter; reset by init_k each launch)
        __threadfence();
        __syncthreads();
        if (tid == 0) {
            atomicAdd(&g_barcnt, 1u);
            const unsigned target = nblk * (unsigned)(t + 1);
            while (*((volatile unsigned*)&g_barcnt) < target) { __nanosleep(32); }
        }
        __syncthreads();
        __threadfence();
    }
}

// ---------------------------------------------------------------------------
extern "C" void kernel_launch(void* const* d_in, const int* in_sizes, int n_in,
                              void* d_out, int out_size)
{
    const int*   tokens = (const int*)  d_in[0];
    const float* emb    = (const float*)d_in[1];
    const float* W0     = (const float*)d_in[2];
    const float* U0     = (const float*)d_in[3];
    const float* b0     = (const float*)d_in[4];
    const float* W1     = (const float*)d_in[5];
    const float* U1     = (const float*)d_in[6];
    const float* b1     = (const float*)d_in[7];
    float* out = (float*)d_out;

    dim3 gg(G3 / 128, SEQ);

    // layer 0: xg = gather(emb, tokens) @ W0 + b0[0]
    gemm_proj<<<gg, 256>>>(emb, tokens, W0, b0, HID, 0);
    init_k<<<32, 256>>>();
    gru_scan<<<NBLK, 256>>>(U0, b0 + G3, 0, nullptr);

    // layer 1: xg = y0 @ W1 + b1[0]   (g_xg reused)
    gemm_proj<<<gg, 256>>>(nullptr, nullptr, W1, b1, UN, 1);
    init_k<<<32, 256>>>();
    gru_scan<<<NBLK, 256>>>(U1, b1 + G3, 1, out);
}